// round 2
// baseline (speedup 1.0000x reference)
#include <cuda_runtime.h>

#define B 32
#define M 32
#define C 1024
#define R 28
#define INV_R2 (1.0f / (R * R))

#define IMGS_PER_BLK 8
#define ROWS_PER_BLK (IMGS_PER_BLK * R)          // 224
#define FLOATS_PER_BLK (ROWS_PER_BLK * R)        // 6272
#define F4_PER_BLK (FLOATS_PER_BLK / 4)          // 1568
#define THREADS 224
#define F4_PER_THREAD (F4_PER_BLK / THREADS)     // 7
#define BLKS_PER_B (C / IMGS_PER_BLK)            // 128

// Scratch (allocation-free rule: __device__ global)
__device__ float g_col[B * M * R];   // column sums of Masks: (B, M, R)

// ---------------------------------------------------------------------------
// Kernel 1: col[b,m,j] = sum_i Masks[b,m,i,j].  3.2 MB, tiny.
// One thread per (b,m,j); 28 independent strided loads (MLP=28), coalesced
// across j within a warp.
// ---------------------------------------------------------------------------
__global__ void reduce_M_kernel(const float* __restrict__ Mk) {
    int tid = blockIdx.x * blockDim.x + threadIdx.x;
    if (tid >= B * M * R) return;
    int j  = tid % R;
    int bm = tid / R;
    const float* p = Mk + (size_t)bm * R * R + j;
    float s = 0.0f;
#pragma unroll
    for (int i = 0; i < R; i++) s += p[i * R];
    g_col[tid] = s;
}

// ---------------------------------------------------------------------------
// Kernel 2 (fused): stream F coalesced -> smem tile of 8 whole images ->
// row sums -> einsum tail, all in one block.
//
//  - Global loads: 7x LDG.128 per thread, warp reads 512B contiguous
//    (4 L1tex wavefronts per LDG, vs 28 in the uncoalesced version).
//  - Row-sum read-back: thread t reads 7x LDS.128 at byte 112*t + 16*k.
//    Per 8-lane phase, f4-bank-group = 7*t mod 8 (permutation) => conflict-free.
//  - Einsum tail: col_s reads broadcast across the 8 c-lanes; rowsum reads
//    hit banks 28*cl mod 32 = {0,28,24,20,16,12,8,4} => conflict-free.
// ---------------------------------------------------------------------------
__global__ void __launch_bounds__(THREADS, 7)
fused_rowsum_einsum_kernel(const float* __restrict__ F, float* __restrict__ out) {
    __shared__ float tile[FLOATS_PER_BLK];    // 25088 B
    __shared__ float rowsum[ROWS_PER_BLK];    // 224 floats: [c_local*28 + i]
    __shared__ float col_s[M * R];            // 896 floats: [m*28 + r]

    const int tid = threadIdx.x;
    const int blk = blockIdx.x;
    const int b   = blk / BLKS_PER_B;

    // Stage col[b] (896 floats, L2-hot: 128 blocks share it)
    {
        const float* cp = g_col + b * (M * R);
#pragma unroll
        for (int k = 0; k < 4; k++)
            col_s[k * THREADS + tid] = cp[k * THREADS + tid];
    }

    // Coalesced streaming load of the 8-image tile
    const float4* src = reinterpret_cast<const float4*>(F) + (size_t)blk * F4_PER_BLK;
    float4* dst = reinterpret_cast<float4*>(tile);
    float4 v[F4_PER_THREAD];
#pragma unroll
    for (int k = 0; k < F4_PER_THREAD; k++) v[k] = src[k * THREADS + tid];
#pragma unroll
    for (int k = 0; k < F4_PER_THREAD; k++) dst[k * THREADS + tid] = v[k];
    __syncthreads();

    // Row sums: thread t sums row t (28 contiguous floats = 7 f4, row-aligned
    // since each row is exactly 7 float4)
    {
        const float4* rp = reinterpret_cast<const float4*>(tile) + tid * (R / 4);
        float s = 0.0f;
#pragma unroll
        for (int k = 0; k < R / 4; k++) {
            float4 w = rp[k];
            s += (w.x + w.y) + (w.z + w.w);
        }
        rowsum[tid] = s;
    }
    __syncthreads();

    // Einsum tail: 256 outputs = 32 m x 8 c_local
    const int c0 = (blk % BLKS_PER_B) * IMGS_PER_BLK;
    for (int o = tid; o < M * IMGS_PER_BLK; o += THREADS) {
        int m  = o / IMGS_PER_BLK;
        int cl = o % IMGS_PER_BLK;
        float acc = 0.0f;
#pragma unroll
        for (int r = 0; r < R; r++)
            acc += col_s[m * R + r] * rowsum[cl * R + r];
        out[((size_t)b * M + m) * C + c0 + cl] = acc * INV_R2;
    }
}

extern "C" void kernel_launch(void* const* d_in, const int* in_sizes, int n_in,
                              void* d_out, int out_size) {
    const float* F  = (const float*)d_in[0];  // (B, C, R, R)
    const float* Mk = (const float*)d_in[1];  // (B, M, R, R)
    float* out = (float*)d_out;               // (B, M, C)

    {
        int n = B * M * R;  // 28672
        reduce_M_kernel<<<(n + 255) / 256, 256>>>(Mk);
    }
    {
        int nblks = (B * C) / IMGS_PER_BLK;   // 4096
        fused_rowsum_einsum_kernel<<<nblks, THREADS>>>(F, out);
    }
}

// round 3
// speedup vs baseline: 1.5273x; 1.5273x over previous
#include <cuda_runtime.h>

#define B 32
#define M 32
#define C 1024
#define R 28
#define INV_R2 (1.0f / (R * R))

#define IMGS_PER_BLK 8
#define ROWS_PER_BLK (IMGS_PER_BLK * R)          // 224
#define F4_PER_BLK (ROWS_PER_BLK * R / 4)        // 1568
#define THREADS 224
#define F4_PER_THREAD (F4_PER_BLK / THREADS)     // 7
#define BLKS_PER_B (C / IMGS_PER_BLK)            // 128

// Scratch (allocation-free rule: __device__ global)
__device__ float g_col[B * M * R];   // column sums of Masks: (B, M, R)

// ---------------------------------------------------------------------------
// Kernel 1: col[b,m,j] = sum_i Masks[b,m,i,j].  3.2 MB, tiny.
// ---------------------------------------------------------------------------
__global__ void reduce_M_kernel(const float* __restrict__ Mk) {
    int tid = blockIdx.x * blockDim.x + threadIdx.x;
    if (tid >= B * M * R) return;
    int j  = tid % R;
    int bm = tid / R;
    const float* p = Mk + (size_t)bm * R * R + j;
    float s = 0.0f;
#pragma unroll
    for (int i = 0; i < R; i++) s += p[i * R];
    g_col[tid] = s;
}

// ---------------------------------------------------------------------------
// Kernel 2 (fused): coalesced stream of F, immediate f4 horizontal sum,
// ONLY scalar partials go through smem (6.3 KB, not 25 KB), then segmented
// row-sum + einsum tail.
//
//  - LDG.128: warp reads 512B contiguous (4 lines/LDG).
//  - partial STS.32 at k*224+tid: stride-1 across lanes -> conflict-free.
//  - read-back: thread t reads partial[7t+k]; bank = (7t+k) mod 32, and
//    7 is coprime to 32 -> per-phase bank permutation -> conflict-free.
//  - smem total ~11 KB -> 9 blocks/SM -> ~63 warps: continuous LDG issue.
// ---------------------------------------------------------------------------
__global__ void __launch_bounds__(THREADS)
fused_rowsum_einsum_kernel(const float* __restrict__ F, float* __restrict__ out) {
    __shared__ float partial[F4_PER_BLK];     // 1568 floats = 6.3 KB
    __shared__ float rowsum[ROWS_PER_BLK];    // 224 floats: [c_local*28 + i]
    __shared__ float col_s[M * R];            // 896 floats: [m*28 + r]

    const int tid = threadIdx.x;
    const int blk = blockIdx.x;
    const int b   = blk / BLKS_PER_B;

    // Stage col[b] (L2-hot: 128 blocks share it)
    {
        const float* cp = g_col + b * (M * R);
#pragma unroll
        for (int k = 0; k < 4; k++)
            col_s[k * THREADS + tid] = cp[k * THREADS + tid];
    }

    // Coalesced streaming load + immediate horizontal sum -> scalar partials
    const float4* src = reinterpret_cast<const float4*>(F) + (size_t)blk * F4_PER_BLK;
    float4 v[F4_PER_THREAD];
#pragma unroll
    for (int k = 0; k < F4_PER_THREAD; k++) v[k] = src[k * THREADS + tid];
#pragma unroll
    for (int k = 0; k < F4_PER_THREAD; k++)
        partial[k * THREADS + tid] = (v[k].x + v[k].y) + (v[k].z + v[k].w);
    __syncthreads();

    // Segmented row sum: row t = partial[7t .. 7t+6]  (7 f4-partials per row)
    {
        float s = 0.0f;
#pragma unroll
        for (int k = 0; k < F4_PER_THREAD; k++) s += partial[tid * F4_PER_THREAD + k];
        rowsum[tid] = s;
    }
    __syncthreads();

    // Einsum tail: 256 outputs = 32 m x 8 c_local
    const int c0 = (blk % BLKS_PER_B) * IMGS_PER_BLK;
    for (int o = tid; o < M * IMGS_PER_BLK; o += THREADS) {
        int m  = o / IMGS_PER_BLK;
        int cl = o % IMGS_PER_BLK;
        float acc = 0.0f;
#pragma unroll
        for (int r = 0; r < R; r++)
            acc += col_s[m * R + r] * rowsum[cl * R + r];
        out[((size_t)b * M + m) * C + c0 + cl] = acc * INV_R2;
    }
}

extern "C" void kernel_launch(void* const* d_in, const int* in_sizes, int n_in,
                              void* d_out, int out_size) {
    const float* F  = (const float*)d_in[0];  // (B, C, R, R)
    const float* Mk = (const float*)d_in[1];  // (B, M, R, R)
    float* out = (float*)d_out;               // (B, M, C)

    {
        int n = B * M * R;  // 28672
        reduce_M_kernel<<<(n + 255) / 256, 256>>>(Mk);
    }
    {
        int nblks = (B * C) / IMGS_PER_BLK;   // 4096
        fused_rowsum_einsum_kernel<<<nblks, THREADS>>>(F, out);
    }
}